// round 7
// baseline (speedup 1.0000x reference)
#include <cuda_runtime.h>
#include <cstdint>

#define CIN   8
#define COUT  8
#define HH    1024
#define WW    1024
#define KK    31
#define PAD   15

#define TILE_X 64
#define TILE_Y 32
#define NTHREADS 256

// smem input tile: rows = TILE_Y + 30 = 62, cols padded to 100 (need 94).
// 100 mod 32 = 4 -> adjacent rows shift banks by 4, killing row conflicts.
#define SROWS 62
#define SCOLS 100

// weights for one ci, packed over co-pairs:
// s_w[(i*32 + j)*4 + cp] = (w[2cp][i][j], w[2cp+1][i][j]); j padded to 32 (j=31 -> 0)
#define NW (31 * 32 * 4)

__device__ __forceinline__ unsigned long long f32x2_dup(float v) {
    unsigned long long r;
    asm("mov.b64 %0, {%1, %1};" : "=l"(r) : "f"(v));
    return r;
}

__device__ __forceinline__ unsigned long long f32x2_pack(float lo, float hi) {
    unsigned long long r;
    asm("mov.b64 %0, {%1, %2};" : "=l"(r) : "f"(lo), "f"(hi));
    return r;
}

__device__ __forceinline__ void f32x2_fma(unsigned long long& acc,
                                          unsigned long long a,
                                          unsigned long long b) {
    asm("fma.rn.f32x2 %0, %1, %2, %0;" : "+l"(acc) : "l"(a), "l"(b));
}

__device__ __forceinline__ void f32x2_unpack(unsigned long long v, float& lo, float& hi) {
    asm("mov.b64 {%0, %1}, %2;" : "=f"(lo), "=f"(hi) : "l"(v));
}

__global__ __launch_bounds__(NTHREADS, 2)
void fftconv_direct_kernel(const float* __restrict__ sig,
                           const float* __restrict__ wgt,
                           const float* __restrict__ bias,
                           float* __restrict__ out)
{
    __shared__ float s_in[SROWS * SCOLS];
    __shared__ unsigned long long s_w[NW];

    const int t  = threadIdx.x;
    const int tx = t & 7;         // 8 threads across x, 8 cols each
    const int ty = t >> 3;        // 32 threads down y, 1 row each
    const int x0 = blockIdx.x * TILE_X;
    const int y0 = blockIdx.y * TILE_Y;
    const int ci = blockIdx.z;

    // acc[cp][p]: packed (out[2cp], out[2cp+1]) for pixel p of this thread's row
    unsigned long long acc[4][8];
#pragma unroll
    for (int cp = 0; cp < 4; ++cp)
#pragma unroll
        for (int p = 0; p < 8; ++p)
            acc[cp][p] = 0ULL;

    // ---- stage input tile for this ci (zero-padded at borders) ----
    const float* sigc = sig + (size_t)ci * (HH * WW);
    for (int idx = t; idx < SROWS * SCOLS; idx += NTHREADS) {
        const int r  = idx / SCOLS;
        const int c  = idx - r * SCOLS;
        const int gr = y0 + r - PAD;
        const int gc = x0 + c - PAD;
        float v = 0.0f;
        if ((unsigned)gr < (unsigned)HH && (unsigned)gc < (unsigned)WW)
            v = sigc[gr * WW + gc];
        s_in[idx] = v;
    }
    // ---- stage co-paired weights for this ci ----
    for (int idx = t; idx < NW; idx += NTHREADS) {
        const int i   = idx >> 7;        // /128 (32 j * 4 cp per i)
        const int rem = idx & 127;
        const int j   = rem >> 2;
        const int cp  = rem & 3;
        float w0 = 0.0f, w1 = 0.0f;
        if (j < KK) {
            const int co0 = 2 * cp;
            w0 = wgt[((co0 * CIN + ci) * KK + i) * KK + j];
            w1 = wgt[(((co0 + 1) * CIN + ci) * KK + i) * KK + j];
        }
        s_w[idx] = f32x2_pack(w0, w1);
    }
    __syncthreads();

#pragma unroll 1
    for (int i = 0; i < KK; ++i) {
        const float* rp = s_in + (ty + i) * SCOLS + 8 * tx;
        const unsigned long long* wrow = s_w + i * 128;   // 32 j * 4 cp

#pragma unroll
        for (int jc = 0; jc < 32; jc += 8) {
            // window cols 8tx+jc .. 8tx+jc+14 -> load 16, duplicate once each
            unsigned long long d[16];
            {
                float4 f0 = *(const float4*)(rp + jc);
                d[0] = f32x2_dup(f0.x); d[1] = f32x2_dup(f0.y);
                d[2] = f32x2_dup(f0.z); d[3] = f32x2_dup(f0.w);
                float4 f1 = *(const float4*)(rp + jc + 4);
                d[4] = f32x2_dup(f1.x); d[5] = f32x2_dup(f1.y);
                d[6] = f32x2_dup(f1.z); d[7] = f32x2_dup(f1.w);
                float4 f2 = *(const float4*)(rp + jc + 8);
                d[8]  = f32x2_dup(f2.x); d[9]  = f32x2_dup(f2.y);
                d[10] = f32x2_dup(f2.z); d[11] = f32x2_dup(f2.w);
                float4 f3 = *(const float4*)(rp + jc + 12);
                d[12] = f32x2_dup(f3.x); d[13] = f32x2_dup(f3.y);
                d[14] = f32x2_dup(f3.z); d[15] = f32x2_dup(f3.w);
            }

#pragma unroll
            for (int j = 0; j < 8; ++j) {
                // 2x LDS.128 broadcast: weights for 4 co-pairs at this (i, jc+j)
                const ulonglong2 w01 = *(const ulonglong2*)(wrow + (jc + j) * 4);
                const ulonglong2 w23 = *(const ulonglong2*)(wrow + (jc + j) * 4 + 2);
#pragma unroll
                for (int p = 0; p < 8; ++p) {
                    const unsigned long long dv = d[j + p];
                    f32x2_fma(acc[0][p], dv, w01.x);
                    f32x2_fma(acc[1][p], dv, w01.y);
                    f32x2_fma(acc[2][p], dv, w23.x);
                    f32x2_fma(acc[3][p], dv, w23.y);
                }
            }
        }
    }

    // ---- epilogue: out[co][ci][y][x] = acc + bias[ci] ----
    const int gy = y0 + ty;
    const int gx = x0 + 8 * tx;
    const float bv = bias[ci];
#pragma unroll
    for (int cp = 0; cp < 4; ++cp) {
        float lo[8], hi[8];
#pragma unroll
        for (int p = 0; p < 8; ++p)
            f32x2_unpack(acc[cp][p], lo[p], hi[p]);

        const int co0 = 2 * cp;
        float* o0 = out + (((size_t)co0       * CIN + ci) * HH + gy) * WW + gx;
        float* o1 = out + (((size_t)(co0 + 1) * CIN + ci) * HH + gy) * WW + gx;
        *(float4*)(o0)     = make_float4(lo[0] + bv, lo[1] + bv, lo[2] + bv, lo[3] + bv);
        *(float4*)(o0 + 4) = make_float4(lo[4] + bv, lo[5] + bv, lo[6] + bv, lo[7] + bv);
        *(float4*)(o1)     = make_float4(hi[0] + bv, hi[1] + bv, hi[2] + bv, hi[3] + bv);
        *(float4*)(o1 + 4) = make_float4(hi[4] + bv, hi[5] + bv, hi[6] + bv, hi[7] + bv);
    }
}

extern "C" void kernel_launch(void* const* d_in, const int* in_sizes, int n_in,
                              void* d_out, int out_size)
{
    const float* sig  = (const float*)d_in[0];   // [1, 8, 1024, 1024]
    const float* wgt  = (const float*)d_in[1];   // [8, 8, 31, 31]
    const float* bias = (const float*)d_in[2];   // [8]
    float* out = (float*)d_out;                  // [8, 8, 1024, 1024]  (co, ci, y, x)

    dim3 grid(WW / TILE_X, HH / TILE_Y, CIN);    // (16, 32, 8) = 4096 blocks
    fftconv_direct_kernel<<<grid, NTHREADS>>>(sig, wgt, bias, out);
}

// round 8
// speedup vs baseline: 1.0030x; 1.0030x over previous
#include <cuda_runtime.h>
#include <cstdint>

#define CIN   8
#define COUT  8
#define HH    1024
#define WW    1024
#define KK    31
#define PAD   15

#define TILE_X 64
#define TILE_Y 32
#define NTHREADS 256

// smem input tile: rows = TILE_Y + 30 = 62, cols padded to 100 (need 94).
// 100 mod 32 = 4 -> adjacent rows shift banks by 4, killing row conflicts.
#define SROWS 62
#define SCOLS 100

// weights for one ci, packed over co-pairs:
// s_w[(i*32 + j)*4 + cp] = (w[2cp][i][j], w[2cp+1][i][j]); j padded to 32 (j=31 -> 0)
#define NW (31 * 32 * 4)

__device__ __forceinline__ unsigned long long f32x2_dup(float v) {
    unsigned long long r;
    asm("mov.b64 %0, {%1, %1};" : "=l"(r) : "f"(v));
    return r;
}

__device__ __forceinline__ unsigned long long f32x2_pack(float lo, float hi) {
    unsigned long long r;
    asm("mov.b64 %0, {%1, %2};" : "=l"(r) : "f"(lo), "f"(hi));
    return r;
}

__device__ __forceinline__ void f32x2_fma(unsigned long long& acc,
                                          unsigned long long a,
                                          unsigned long long b) {
    asm("fma.rn.f32x2 %0, %1, %2, %0;" : "+l"(acc) : "l"(a), "l"(b));
}

__device__ __forceinline__ void f32x2_unpack(unsigned long long v, float& lo, float& hi) {
    asm("mov.b64 {%0, %1}, %2;" : "=f"(lo), "=f"(hi) : "l"(v));
}

__global__ __launch_bounds__(NTHREADS, 2)
void fftconv_direct_kernel(const float* __restrict__ sig,
                           const float* __restrict__ wgt,
                           const float* __restrict__ bias,
                           float* __restrict__ out)
{
    __shared__ float s_in[SROWS * SCOLS];
    __shared__ unsigned long long s_w[NW];

    const int t  = threadIdx.x;
    const int tx = t & 7;         // 8 threads across x, 8 cols each
    const int ty = t >> 3;        // 32 threads down y, 1 row each
    const int x0 = blockIdx.x * TILE_X;
    const int y0 = blockIdx.y * TILE_Y;
    const int ci = blockIdx.z;

    // acc[cp][p]: packed (out[2cp], out[2cp+1]) for pixel p of this thread's row
    unsigned long long acc[4][8];
#pragma unroll
    for (int cp = 0; cp < 4; ++cp)
#pragma unroll
        for (int p = 0; p < 8; ++p)
            acc[cp][p] = 0ULL;

    // ---- stage input tile for this ci (zero-padded at borders) ----
    const float* sigc = sig + (size_t)ci * (HH * WW);
    for (int idx = t; idx < SROWS * SCOLS; idx += NTHREADS) {
        const int r  = idx / SCOLS;
        const int c  = idx - r * SCOLS;
        const int gr = y0 + r - PAD;
        const int gc = x0 + c - PAD;
        float v = 0.0f;
        if ((unsigned)gr < (unsigned)HH && (unsigned)gc < (unsigned)WW)
            v = sigc[gr * WW + gc];
        s_in[idx] = v;
    }
    // ---- stage co-paired weights for this ci ----
    for (int idx = t; idx < NW; idx += NTHREADS) {
        const int i   = idx >> 7;        // /128 (32 j * 4 cp per i)
        const int rem = idx & 127;
        const int j   = rem >> 2;
        const int cp  = rem & 3;
        float w0 = 0.0f, w1 = 0.0f;
        if (j < KK) {
            const int co0 = 2 * cp;
            w0 = wgt[((co0 * CIN + ci) * KK + i) * KK + j];
            w1 = wgt[(((co0 + 1) * CIN + ci) * KK + i) * KK + j];
        }
        s_w[idx] = f32x2_pack(w0, w1);
    }
    __syncthreads();

#pragma unroll 1
    for (int i = 0; i < KK; ++i) {
        const float* rp = s_in + (ty + i) * SCOLS + 8 * tx;
        const unsigned long long* wrow = s_w + i * 128;   // 32 j * 4 cp

#pragma unroll
        for (int jc = 0; jc < 32; jc += 8) {
            // window cols 8tx+jc .. 8tx+jc+14 -> load 16, duplicate once each
            unsigned long long d[16];
            {
                float4 f0 = *(const float4*)(rp + jc);
                d[0] = f32x2_dup(f0.x); d[1] = f32x2_dup(f0.y);
                d[2] = f32x2_dup(f0.z); d[3] = f32x2_dup(f0.w);
                float4 f1 = *(const float4*)(rp + jc + 4);
                d[4] = f32x2_dup(f1.x); d[5] = f32x2_dup(f1.y);
                d[6] = f32x2_dup(f1.z); d[7] = f32x2_dup(f1.w);
                float4 f2 = *(const float4*)(rp + jc + 8);
                d[8]  = f32x2_dup(f2.x); d[9]  = f32x2_dup(f2.y);
                d[10] = f32x2_dup(f2.z); d[11] = f32x2_dup(f2.w);
                float4 f3 = *(const float4*)(rp + jc + 12);
                d[12] = f32x2_dup(f3.x); d[13] = f32x2_dup(f3.y);
                d[14] = f32x2_dup(f3.z); d[15] = f32x2_dup(f3.w);
            }

#pragma unroll
            for (int j = 0; j < 8; ++j) {
                // 2x LDS.128 broadcast: weights for 4 co-pairs at this (i, jc+j)
                const ulonglong2 w01 = *(const ulonglong2*)(wrow + (jc + j) * 4);
                const ulonglong2 w23 = *(const ulonglong2*)(wrow + (jc + j) * 4 + 2);
#pragma unroll
                for (int p = 0; p < 8; ++p) {
                    const unsigned long long dv = d[j + p];
                    f32x2_fma(acc[0][p], dv, w01.x);
                    f32x2_fma(acc[1][p], dv, w01.y);
                    f32x2_fma(acc[2][p], dv, w23.x);
                    f32x2_fma(acc[3][p], dv, w23.y);
                }
            }
        }
    }

    // ---- epilogue: out[co][ci][y][x] = acc + bias[ci] ----
    const int gy = y0 + ty;
    const int gx = x0 + 8 * tx;
    const float bv = bias[ci];
#pragma unroll
    for (int cp = 0; cp < 4; ++cp) {
        float lo[8], hi[8];
#pragma unroll
        for (int p = 0; p < 8; ++p)
            f32x2_unpack(acc[cp][p], lo[p], hi[p]);

        const int co0 = 2 * cp;
        float* o0 = out + (((size_t)co0       * CIN + ci) * HH + gy) * WW + gx;
        float* o1 = out + (((size_t)(co0 + 1) * CIN + ci) * HH + gy) * WW + gx;
        *(float4*)(o0)     = make_float4(lo[0] + bv, lo[1] + bv, lo[2] + bv, lo[3] + bv);
        *(float4*)(o0 + 4) = make_float4(lo[4] + bv, lo[5] + bv, lo[6] + bv, lo[7] + bv);
        *(float4*)(o1)     = make_float4(hi[0] + bv, hi[1] + bv, hi[2] + bv, hi[3] + bv);
        *(float4*)(o1 + 4) = make_float4(hi[4] + bv, hi[5] + bv, hi[6] + bv, hi[7] + bv);
    }
}

extern "C" void kernel_launch(void* const* d_in, const int* in_sizes, int n_in,
                              void* d_out, int out_size)
{
    const float* sig  = (const float*)d_in[0];   // [1, 8, 1024, 1024]
    const float* wgt  = (const float*)d_in[1];   // [8, 8, 31, 31]
    const float* bias = (const float*)d_in[2];   // [8]
    float* out = (float*)d_out;                  // [8, 8, 1024, 1024]  (co, ci, y, x)

    dim3 grid(WW / TILE_X, HH / TILE_Y, CIN);    // (16, 32, 8) = 4096 blocks
    fftconv_direct_kernel<<<grid, NTHREADS>>>(sig, wgt, bias, out);
}

// round 10
// speedup vs baseline: 2.8464x; 2.8379x over previous
#include <cuda_runtime.h>
#include <cstdint>

#define CIN  8
#define COUT 8
#define HH   1024
#define WW   1024
#define KK   31

#define NT   256                 // 8 warps
#define RY   8                   // output rows per CTA
#define TXC  256                 // output cols per CTA (8 warps x 32 px)
#define NROWS (RY + 30)          // 38 staged input rows
#define NCOLS 288                // staged cols (X0-15 .. X0+272)
#define ROWF  292                // padded row stride in floats
#define ROWB  (ROWF * 4)         // 1168 bytes

#define OFF_SA 0
#define SA_BYTES (NROWS * ROWB)              // 44384
#define OFF_W   ((SA_BYTES + 127) & ~127)    // 44416
#define W_BYTES (31 * 4 * 32 * 8)            // 31744
#define SMEM_TOTAL (OFF_W + W_BYTES)         // 76160

static __device__ __forceinline__ uint32_t smem_u32(const void* p) {
    uint32_t a;
    asm("{ .reg .u64 t; cvta.to.shared.u64 t, %1; cvt.u32.u64 %0, t; }" : "=r"(a) : "l"(p));
    return a;
}
static __device__ __forceinline__ uint32_t cvt_tf32(float f) {
    uint32_t r;
    asm("cvt.rna.tf32.f32 %0, %1;" : "=r"(r) : "f"(f));
    return r;
}
static __device__ __forceinline__ uint32_t lds32(uint32_t a) {
    uint32_t v;
    asm volatile("ld.shared.b32 %0, [%1];" : "=r"(v) : "r"(a));
    return v;
}
static __device__ __forceinline__ uint2 lds64(uint32_t a) {
    uint2 v;
    asm volatile("ld.shared.v2.b32 {%0,%1}, [%2];" : "=r"(v.x), "=r"(v.y) : "r"(a));
    return v;
}
// D(16x8 px,co) += A(16x8 px,k) * B(8x8 k,co)
static __device__ __forceinline__ void mma8(float* c,
                                            uint32_t a0, uint32_t a1,
                                            uint32_t a2, uint32_t a3,
                                            uint2 b) {
    asm volatile("mma.sync.aligned.m16n8k8.row.col.f32.tf32.tf32.f32 "
                 "{%0,%1,%2,%3}, {%4,%5,%6,%7}, {%8,%9}, {%0,%1,%2,%3};"
                 : "+f"(c[0]), "+f"(c[1]), "+f"(c[2]), "+f"(c[3])
                 : "r"(a0), "r"(a1), "r"(a2), "r"(a3), "r"(b.x), "r"(b.y));
}

__global__ __launch_bounds__(NT, 2)
void conv_mma_kernel(const float* __restrict__ sig,
                     const float* __restrict__ wgt,
                     const float* __restrict__ bias,
                     float* __restrict__ out)
{
    extern __shared__ char smem[];
    const uint32_t sb = smem_u32(smem);
    const int tid  = threadIdx.x;
    const int wid  = tid >> 5;
    const int lane = tid & 31;
    const int X0 = blockIdx.x * TXC;
    const int Y0 = blockIdx.y * RY;
    const int ci = blockIdx.z;

    // ---- stage input rows (tf32-rounded, zero-padded) ----
    const float* sigc = sig + (size_t)ci * (HH * WW);
    uint32_t* sa = (uint32_t*)(smem + OFF_SA);
    for (int idx = tid; idx < NROWS * NCOLS; idx += NT) {
        const int rr = idx / NCOLS;
        const int lc = idx - rr * NCOLS;
        const int gr = Y0 - 15 + rr;
        const int gc = X0 - 15 + lc;
        uint32_t v = 0u;
        if ((unsigned)gr < (unsigned)HH && (unsigned)gc < (unsigned)WW)
            v = cvt_tf32(sigc[(size_t)gr * WW + gc]);
        sa[rr * ROWF + lc] = v;
    }

    // ---- stage B fragments: wf[(i*4+t)*32+lane] = (w[n][ci][i][8t+k0], w[..][8t+k0+4]) ----
    // lane: n = lane>>2 (cout), k0 = lane&3
    uint2* wf = (uint2*)(smem + OFF_W);
    for (int idx = tid; idx < 31 * 4 * 32; idx += NT) {
        const int i  = idx >> 7;
        const int t  = (idx >> 5) & 3;
        const int ln = idx & 31;
        const int n  = ln >> 2;
        const int k0 = ln & 3;
        const int j0 = 8 * t + k0;
        const int j1 = j0 + 4;
        const float* wp = wgt + ((size_t)(n * CIN + ci) * KK + i) * KK;
        uint32_t b0 = cvt_tf32(wp[j0]);                       // j0 <= 27 < 31 always
        uint32_t b1 = (j1 < KK) ? cvt_tf32(wp[j1]) : 0u;      // j1 == 31 -> pad 0
        wf[idx] = make_uint2(b0, b1);
    }
    __syncthreads();

    // ---- compute ----
    const int m0  = lane >> 2;      // pixel row within fragment (and +8)
    const int k0l = lane & 3;       // k col within fragment (and +4)

    float acc[2][RY][4];
#pragma unroll
    for (int s = 0; s < 2; ++s)
#pragma unroll
        for (int y = 0; y < RY; ++y)
#pragma unroll
            for (int q = 0; q < 4; ++q)
                acc[s][y][q] = 0.0f;

    // A element (m,k) of strip s, chunk t, input row rr:
    //   sa[rr][wid*32 + s*16 + 8t + m + k]
    const uint32_t a_base = sb + OFF_SA + (uint32_t)(wid * 32 + m0 + k0l) * 4u;
    const uint32_t b_base = sb + OFF_W + (uint32_t)lane * 8u;

    const int rlo = (Y0 - 15 > 0) ? Y0 - 15 : 0;
    const int rhi = (Y0 + RY + 14 < HH - 1) ? Y0 + RY + 14 : HH - 1;

#pragma unroll 1
    for (int r = rlo; r <= rhi; ++r) {
        const int rr  = r - (Y0 - 15);
        const int id0 = r - Y0 + 15;            // i = id0 - y8, valid 0..30
        const uint32_t arow = a_base + (uint32_t)rr * ROWB;

#pragma unroll
        for (int t = 0; t < 4; ++t) {
            // strip 0: cols +8t ; strip 1: +16 more
            const uint32_t p0 = arow + (uint32_t)(8 * t) * 4u;
            const uint32_t p1 = p0 + 64u;
            // fragment regs: a0=[q], a1=[q+8], a2=[q+4], a3=[q+12]
            const uint32_t s0a0 = lds32(p0),      s0a2 = lds32(p0 + 16);
            const uint32_t s0a1 = lds32(p0 + 32), s0a3 = lds32(p0 + 48);
            const uint32_t s1a0 = lds32(p1),      s1a2 = lds32(p1 + 16);
            const uint32_t s1a1 = lds32(p1 + 32), s1a3 = lds32(p1 + 48);

#pragma unroll
            for (int y8 = 0; y8 < RY; ++y8) {
                const int i = id0 - y8;
                if ((unsigned)i <= 30u) {
                    const uint2 b = lds64(b_base + (uint32_t)(i * 1024 + t * 256));
                    mma8(acc[0][y8], s0a0, s0a1, s0a2, s0a3, b);
                    mma8(acc[1][y8], s1a0, s1a1, s1a2, s1a3, b);
                }
            }
        }
    }

    // ---- epilogue: direct stores, D layout c0:(m0,2k0) c1:(m0,2k0+1) c2:(m0+8,2k0) c3:(m0+8,2k0+1) ----
    const float bv  = bias[ci];
    const int co0   = 2 * k0l;
    const size_t plane = (size_t)CIN * HH * WW;   // co stride in elements

#pragma unroll
    for (int s = 0; s < 2; ++s) {
        const int px = X0 + wid * 32 + s * 16 + m0;
#pragma unroll
        for (int y8 = 0; y8 < RY; ++y8) {
            const int y = Y0 + y8;
            float* b0p = out + (((size_t)co0 * CIN + ci) * HH + y) * WW + px;
            float* b1p = b0p + plane;
            b0p[0] = acc[s][y8][0] + bv;
            b1p[0] = acc[s][y8][1] + bv;
            b0p[8] = acc[s][y8][2] + bv;
            b1p[8] = acc[s][y8][3] + bv;
        }
    }
}

extern "C" void kernel_launch(void* const* d_in, const int* in_sizes, int n_in,
                              void* d_out, int out_size)
{
    const float* sig  = (const float*)d_in[0];   // [1, 8, 1024, 1024]
    const float* wgt  = (const float*)d_in[1];   // [8, 8, 31, 31]
    const float* bias = (const float*)d_in[2];   // [8]
    float* out = (float*)d_out;                  // [8, 8, 1024, 1024]

    cudaFuncSetAttribute(conv_mma_kernel,
                         cudaFuncAttributeMaxDynamicSharedMemorySize, SMEM_TOTAL);
    dim3 grid(WW / TXC, HH / RY, CIN);           // (4, 128, 8) = 4096 blocks
    conv_mma_kernel<<<grid, NT, SMEM_TOTAL>>>(sig, wgt, bias, out);
}

// round 11
// speedup vs baseline: 4.2918x; 1.5078x over previous
#include <cuda_runtime.h>
#include <cstdint>

#define CIN  8
#define COUT 8
#define HH   1024
#define WW   1024
#define KK   31

#define NT   256                 // 8 warps
#define RY   8                   // output rows per CTA
#define TXC  256                 // output cols per CTA (8 warps x 32 px)
#define NROWS (RY + 30)          // 38 staged input rows
#define NHALF 289                // staged halves per row: local col 0..288
#define WPC   146                // packed words per parity copy
#define ROWB  (2 * WPC * 4)      // 1168 bytes per row (copy0[146], copy1[146])

#define OFF_SA 0
#define SA_BYTES (NROWS * ROWB)              // 44384
#define OFF_W   ((SA_BYTES + 127) & ~127)    // 44416
#define W_BYTES (31 * 2 * 32 * 8)            // 15872
#define SMEM_TOTAL (OFF_W + W_BYTES)         // 60288

static __device__ __forceinline__ uint32_t smem_u32(const void* p) {
    uint32_t a;
    asm("{ .reg .u64 t; cvta.to.shared.u64 t, %1; cvt.u32.u64 %0, t; }" : "=r"(a) : "l"(p));
    return a;
}
// pack two fp32 -> (f16lo, f16hi) in one b32
static __device__ __forceinline__ uint32_t packh(float lo, float hi) {
    uint32_t r;
    asm("{ .reg .f16 l, h; cvt.rn.f16.f32 l, %1; cvt.rn.f16.f32 h, %2; mov.b32 %0, {l, h}; }"
        : "=r"(r) : "f"(lo), "f"(hi));
    return r;
}
static __device__ __forceinline__ uint32_t lds32(uint32_t a) {
    uint32_t v;
    asm volatile("ld.shared.b32 %0, [%1];" : "=r"(v) : "r"(a));
    return v;
}
static __device__ __forceinline__ uint2 lds64(uint32_t a) {
    uint2 v;
    asm volatile("ld.shared.v2.b32 {%0,%1}, [%2];" : "=r"(v.x), "=r"(v.y) : "r"(a));
    return v;
}
// D(16px x 8co) += A(16px x 16k) * B(16k x 8co), fp16 in, fp32 acc
static __device__ __forceinline__ void mma16(float* c,
                                             uint32_t a0, uint32_t a1,
                                             uint32_t a2, uint32_t a3,
                                             uint2 b) {
    asm volatile("mma.sync.aligned.m16n8k16.row.col.f32.f16.f16.f32 "
                 "{%0,%1,%2,%3}, {%4,%5,%6,%7}, {%8,%9}, {%0,%1,%2,%3};"
                 : "+f"(c[0]), "+f"(c[1]), "+f"(c[2]), "+f"(c[3])
                 : "r"(a0), "r"(a1), "r"(a2), "r"(a3), "r"(b.x), "r"(b.y));
}

__global__ __launch_bounds__(NT, 2)
void conv_mma_kernel(const float* __restrict__ sig,
                     const float* __restrict__ wgt,
                     const float* __restrict__ bias,
                     float* __restrict__ out)
{
    extern __shared__ char smem[];
    const uint32_t sb = smem_u32(smem);
    const int tid  = threadIdx.x;
    const int wid  = tid >> 5;
    const int lane = tid & 31;
    const int X0 = blockIdx.x * TXC;
    const int Y0 = blockIdx.y * RY;
    const int ci = blockIdx.z;

    // ---- stage input rows as fp16, two parity-shifted packed copies ----
    // h[lc] = sig[gr][X0-16+lc], lc in [0,289)
    // copy0[w] = (h[2w],   h[2w+1]) ; copy1[w] = (h[2w+1], h[2w+2])
    const float* sigc = sig + (size_t)ci * (HH * WW);
    for (int idx = tid; idx < NROWS * 2 * WPC; idx += NT) {
        const int rr  = idx / (2 * WPC);
        const int rem = idx - rr * (2 * WPC);
        const int cp  = rem / WPC;
        const int w   = rem - cp * WPC;
        const int gr  = Y0 - 15 + rr;
        const int lc0 = 2 * w + cp;
        float v0 = 0.0f, v1 = 0.0f;
        if ((unsigned)gr < (unsigned)HH) {
            const float* srow = sigc + (size_t)gr * WW;
            const int g0 = X0 - 16 + lc0;
            const int g1 = g0 + 1;
            if ((unsigned)g0 < (unsigned)WW) v0 = srow[g0];
            if ((unsigned)g1 < (unsigned)WW) v1 = srow[g1];
        }
        ((uint32_t*)(smem + OFF_SA))[rr * (2 * WPC) + cp * WPC + w] = packh(v0, v1);
    }

    // ---- stage B fragments per lane: n = lane>>2, k0 = lane&3 ----
    // wf[(i*2+t)*32+lane] = ( pack(w[j],w[j+1]), pack(w[j+8],w[j+9]) ), j = 16t+2k0
    uint2* wf = (uint2*)(smem + OFF_W);
    for (int idx = tid; idx < 31 * 2 * 32; idx += NT) {
        const int i  = idx >> 6;
        const int t  = (idx >> 5) & 1;
        const int ln = idx & 31;
        const int n  = ln >> 2;
        const int k0 = ln & 3;
        const int j  = 16 * t + 2 * k0;
        const float* wp = wgt + ((size_t)(n * CIN + ci) * KK + i) * KK;
        const float w0 = wp[j];
        const float w1 = wp[j + 1];
        const float w2 = wp[j + 8];
        const float w3 = (j + 9 < KK) ? wp[j + 9] : 0.0f;   // tap 31 padded
        wf[idx] = make_uint2(packh(w0, w1), packh(w2, w3));
    }
    __syncthreads();

    // ---- compute ----
    const int m0  = lane >> 2;
    const int k0l = lane & 3;
    const int par = (m0 + 1) & 1;

    float acc[2][RY][4];
#pragma unroll
    for (int s = 0; s < 2; ++s)
#pragma unroll
        for (int y = 0; y < RY; ++y)
#pragma unroll
            for (int q = 0; q < 4; ++q)
                acc[s][y][q] = 0.0f;

    // A pair base (halves): lq = wid*32 + s*16 + 16t + 1 + m0 + 2*k0l
    // byte offset within row = par*584 + ((lq-par)>>1)*4 ; +8 halves -> +16B ; +16 -> +32B
    uint32_t aoff[2][2];
#pragma unroll
    for (int s = 0; s < 2; ++s)
#pragma unroll
        for (int t = 0; t < 2; ++t) {
            const int lq = wid * 32 + s * 16 + 16 * t + 1 + m0 + 2 * k0l;
            aoff[s][t] = (uint32_t)(par * (WPC * 4) + (((lq - par) >> 1) << 2));
        }
    const uint32_t sa_base = sb + OFF_SA;
    const uint32_t b_base  = sb + OFF_W + (uint32_t)lane * 8u;

    const int rlo = (Y0 - 15 > 0) ? Y0 - 15 : 0;
    const int rhi = (Y0 + RY + 14 < HH - 1) ? Y0 + RY + 14 : HH - 1;

#pragma unroll 1
    for (int r = rlo; r <= rhi; ++r) {
        const int rr  = r - (Y0 - 15);
        const int id0 = r - Y0 + 15;                 // i = id0 - y8, valid 0..30
        const uint32_t arow = sa_base + (uint32_t)rr * ROWB;

#pragma unroll
        for (int t = 0; t < 2; ++t) {
            // Toeplitz: a1 (m+8) == a2 (k+8) -> 3 loads per strip
            const uint32_t p0 = arow + aoff[0][t];
            const uint32_t p1 = arow + aoff[1][t];
            const uint32_t s0a0 = lds32(p0), s0aM = lds32(p0 + 16), s0a3 = lds32(p0 + 32);
            const uint32_t s1a0 = lds32(p1), s1aM = lds32(p1 + 16), s1a3 = lds32(p1 + 32);

#pragma unroll
            for (int y8 = 0; y8 < RY; ++y8) {
                const int i = id0 - y8;
                if ((unsigned)i <= 30u) {
                    const uint2 b = lds64(b_base + (uint32_t)((i * 2 + t) * 256));
                    mma16(acc[0][y8], s0a0, s0aM, s0aM, s0a3, b);
                    mma16(acc[1][y8], s1a0, s1aM, s1aM, s1a3, b);
                }
            }
        }
    }

    // ---- epilogue: D c0:(m0,2k0) c1:(m0,2k0+1) c2:(m0+8,2k0) c3:(m0+8,2k0+1) ----
    const float bv  = bias[ci];
    const int co0   = 2 * k0l;
    const size_t plane = (size_t)CIN * HH * WW;

#pragma unroll
    for (int s = 0; s < 2; ++s) {
        const int px = X0 + wid * 32 + s * 16 + m0;
#pragma unroll
        for (int y8 = 0; y8 < RY; ++y8) {
            const int y = Y0 + y8;
            float* b0p = out + (((size_t)co0 * CIN + ci) * HH + y) * WW + px;
            float* b1p = b0p + plane;
            b0p[0] = acc[s][y8][0] + bv;
            b1p[0] = acc[s][y8][1] + bv;
            b0p[8] = acc[s][y8][2] + bv;
            b1p[8] = acc[s][y8][3] + bv;
        }
    }
}

extern "C" void kernel_launch(void* const* d_in, const int* in_sizes, int n_in,
                              void* d_out, int out_size)
{
    const float* sig  = (const float*)d_in[0];   // [1, 8, 1024, 1024]
    const float* wgt  = (const float*)d_in[1];   // [8, 8, 31, 31]
    const float* bias = (const float*)d_in[2];   // [8]
    float* out = (float*)d_out;                  // [8, 8, 1024, 1024]

    cudaFuncSetAttribute(conv_mma_kernel,
                         cudaFuncAttributeMaxDynamicSharedMemorySize, SMEM_TOTAL);
    dim3 grid(WW / TXC, HH / RY, CIN);           // (4, 128, 8) = 4096 blocks
    conv_mma_kernel<<<grid, NT, SMEM_TOTAL>>>(sig, wgt, bias, out);
}

// round 12
// speedup vs baseline: 4.3164x; 1.0058x over previous
#include <cuda_runtime.h>
#include <cstdint>

#define CIN  8
#define COUT 8
#define HH   1024
#define WW   1024
#define KK   31

#define NT   256                 // 8 warps
#define RY   8                   // output rows per CTA
#define TXC  256                 // output cols per CTA (8 warps x 32 px)
#define NROWS (RY + 30)          // 38 staged input rows
#define WPC   146                // packed words per parity copy
#define ROWB  (2 * WPC * 4)      // 1168 bytes per row (copy0[146], copy1[146])

#define OFF_SA 0
#define SA_BYTES (NROWS * ROWB)              // 44384
#define OFF_W   ((SA_BYTES + 127) & ~127)    // 44416
#define W_BYTES (31 * 2 * 32 * 8)            // 15872
#define SMEM_TOTAL (OFF_W + W_BYTES)         // 60288

static __device__ __forceinline__ uint32_t smem_u32(const void* p) {
    uint32_t a;
    asm("{ .reg .u64 t; cvta.to.shared.u64 t, %1; cvt.u32.u64 %0, t; }" : "=r"(a) : "l"(p));
    return a;
}
// pack two fp32 -> (f16lo, f16hi) in one b32
static __device__ __forceinline__ uint32_t packh(float lo, float hi) {
    uint32_t r;
    asm("{ .reg .f16 l, h; cvt.rn.f16.f32 l, %1; cvt.rn.f16.f32 h, %2; mov.b32 %0, {l, h}; }"
        : "=r"(r) : "f"(lo), "f"(hi));
    return r;
}
static __device__ __forceinline__ uint32_t lds32(uint32_t a) {
    uint32_t v;
    asm volatile("ld.shared.b32 %0, [%1];" : "=r"(v) : "r"(a));
    return v;
}
static __device__ __forceinline__ uint2 lds64(uint32_t a) {
    uint2 v;
    asm volatile("ld.shared.v2.b32 {%0,%1}, [%2];" : "=r"(v.x), "=r"(v.y) : "r"(a));
    return v;
}
// D(16px x 8co) += A(16px x 16k) * B(16k x 8co), fp16 in, fp32 acc
static __device__ __forceinline__ void mma16(float* c,
                                             uint32_t a0, uint32_t a1,
                                             uint32_t a2, uint32_t a3,
                                             uint2 b) {
    asm volatile("mma.sync.aligned.m16n8k16.row.col.f32.f16.f16.f32 "
                 "{%0,%1,%2,%3}, {%4,%5,%6,%7}, {%8,%9}, {%0,%1,%2,%3};"
                 : "+f"(c[0]), "+f"(c[1]), "+f"(c[2]), "+f"(c[3])
                 : "r"(a0), "r"(a1), "r"(a2), "r"(a3), "r"(b.x), "r"(b.y));
}

__global__ __launch_bounds__(NT, 2)
void conv_mma_kernel(const float* __restrict__ sig,
                     const float* __restrict__ wgt,
                     const float* __restrict__ bias,
                     float* __restrict__ out)
{
    extern __shared__ char smem[];
    const uint32_t sb = smem_u32(smem);
    const int tid  = threadIdx.x;
    const int wid  = tid >> 5;
    const int lane = tid & 31;
    const int X0 = blockIdx.x * TXC;
    const int Y0 = blockIdx.y * RY;
    const int ci = blockIdx.z;

    // ---- stage input rows as fp16, two parity-shifted packed copies ----
    const float* sigc = sig + (size_t)ci * (HH * WW);
    for (int idx = tid; idx < NROWS * 2 * WPC; idx += NT) {
        const int rr  = idx / (2 * WPC);
        const int rem = idx - rr * (2 * WPC);
        const int cp  = rem / WPC;
        const int w   = rem - cp * WPC;
        const int gr  = Y0 - 15 + rr;
        const int lc0 = 2 * w + cp;
        float v0 = 0.0f, v1 = 0.0f;
        if ((unsigned)gr < (unsigned)HH) {
            const float* srow = sigc + (size_t)gr * WW;
            const int g0 = X0 - 16 + lc0;
            const int g1 = g0 + 1;
            if ((unsigned)g0 < (unsigned)WW) v0 = srow[g0];
            if ((unsigned)g1 < (unsigned)WW) v1 = srow[g1];
        }
        ((uint32_t*)(smem + OFF_SA))[rr * (2 * WPC) + cp * WPC + w] = packh(v0, v1);
    }

    // ---- stage B fragments per lane: n = lane>>2, k0 = lane&3 ----
    uint2* wf = (uint2*)(smem + OFF_W);
    for (int idx = tid; idx < 31 * 2 * 32; idx += NT) {
        const int i  = idx >> 6;
        const int t  = (idx >> 5) & 1;
        const int ln = idx & 31;
        const int n  = ln >> 2;
        const int k0 = ln & 3;
        const int j  = 16 * t + 2 * k0;
        const float* wp = wgt + ((size_t)(n * CIN + ci) * KK + i) * KK;
        const float w0 = wp[j];
        const float w1 = wp[j + 1];
        const float w2 = wp[j + 8];
        const float w3 = (j + 9 < KK) ? wp[j + 9] : 0.0f;   // tap 31 padded
        wf[idx] = make_uint2(packh(w0, w1), packh(w2, w3));
    }
    __syncthreads();

    // ---- compute ----
    const int m0  = lane >> 2;
    const int k0l = lane & 3;
    const int par = (m0 + 1) & 1;

    float acc[2][RY][4];
#pragma unroll
    for (int s = 0; s < 2; ++s)
#pragma unroll
        for (int y = 0; y < RY; ++y)
#pragma unroll
            for (int q = 0; q < 4; ++q)
                acc[s][y][q] = 0.0f;

    // A base for strip 0, chunk t: lq = wid*32 + 16t + 1 + m0 + 2*k0l
    // strip 1 = strip 0 + 32B; within-strip regs at +0,+16,+32; boundary shared.
    uint32_t aoff[2];
#pragma unroll
    for (int t = 0; t < 2; ++t) {
        const int lq = wid * 32 + 16 * t + 1 + m0 + 2 * k0l;
        aoff[t] = (uint32_t)(par * (WPC * 4) + (((lq - par) >> 1) << 2));
    }
    const uint32_t sa_base = sb + OFF_SA;
    const uint32_t b_base  = sb + OFF_W + (uint32_t)lane * 8u;

    const int rlo = (Y0 - 15 > 0) ? Y0 - 15 : 0;
    const int rhi = (Y0 + RY + 14 < HH - 1) ? Y0 + RY + 14 : HH - 1;
    // interior: id0 = r - Y0 + 15 in [7, 30] -> all 8 y8 valid
    const int ilo = (rlo > Y0 - 8)  ? rlo : Y0 - 8;
    const int ihi = (rhi < Y0 + 15) ? rhi : Y0 + 15;

    // ---- leading edge rows (guarded) ----
#pragma unroll 1
    for (int r = rlo; r < ilo; ++r) {
        const int rr  = r - (Y0 - 15);
        const int id0 = r - Y0 + 15;
        const uint32_t arow = sa_base + (uint32_t)rr * ROWB;
#pragma unroll
        for (int t = 0; t < 2; ++t) {
            const uint32_t p0 = arow + aoff[t];
            const uint32_t a0 = lds32(p0),      aM = lds32(p0 + 16);
            const uint32_t aX = lds32(p0 + 32), aN = lds32(p0 + 48);
            const uint32_t aZ = lds32(p0 + 64);
#pragma unroll
            for (int y8 = 0; y8 < RY; ++y8) {
                const int i = id0 - y8;
                if ((unsigned)i <= 30u) {
                    const uint2 b = lds64(b_base + (uint32_t)((i * 2 + t) * 256));
                    mma16(acc[0][y8], a0, aM, aM, aX, b);
                    mma16(acc[1][y8], aX, aN, aN, aZ, b);
                }
            }
        }
    }

    // ---- interior rows (branch-free, B prefetched) ----
#pragma unroll 1
    for (int r = ilo; r <= ihi; ++r) {
        const int rr  = r - (Y0 - 15);
        const int id0 = r - Y0 + 15;
        const uint32_t arow = sa_base + (uint32_t)rr * ROWB;
#pragma unroll
        for (int t = 0; t < 2; ++t) {
            const uint32_t p0 = arow + aoff[t];
            const uint32_t a0 = lds32(p0),      aM = lds32(p0 + 16);
            const uint32_t aX = lds32(p0 + 32), aN = lds32(p0 + 48);
            const uint32_t aZ = lds32(p0 + 64);

            uint2 b[RY];
#pragma unroll
            for (int y8 = 0; y8 < RY; ++y8)
                b[y8] = lds64(b_base + (uint32_t)(((id0 - y8) * 2 + t) * 256));

#pragma unroll
            for (int y8 = 0; y8 < RY; ++y8) {
                mma16(acc[0][y8], a0, aM, aM, aX, b[y8]);
                mma16(acc[1][y8], aX, aN, aN, aZ, b[y8]);
            }
        }
    }

    // ---- trailing edge rows (guarded) ----
#pragma unroll 1
    for (int r = ihi + 1; r <= rhi; ++r) {
        const int rr  = r - (Y0 - 15);
        const int id0 = r - Y0 + 15;
        const uint32_t arow = sa_base + (uint32_t)rr * ROWB;
#pragma unroll
        for (int t = 0; t < 2; ++t) {
            const uint32_t p0 = arow + aoff[t];
            const uint32_t a0 = lds32(p0),      aM = lds32(p0 + 16);
            const uint32_t aX = lds32(p0 + 32), aN = lds32(p0 + 48);
            const uint32_t aZ = lds32(p0 + 64);
#pragma unroll
            for (int y8 = 0; y8 < RY; ++y8) {
                const int i = id0 - y8;
                if ((unsigned)i <= 30u) {
                    const uint2 b = lds64(b_base + (uint32_t)((i * 2 + t) * 256));
                    mma16(acc[0][y8], a0, aM, aM, aX, b);
                    mma16(acc[1][y8], aX, aN, aN, aZ, b);
                }
            }
        }
    }

    // ---- epilogue: D c0:(m0,2k0) c1:(m0,2k0+1) c2:(m0+8,2k0) c3:(m0+8,2k0+1) ----
    const float bv  = bias[ci];
    const int co0   = 2 * k0l;
    const size_t plane = (size_t)CIN * HH * WW;

#pragma unroll
    for (int s = 0; s < 2; ++s) {
        const int px = X0 + wid * 32 + s * 16 + m0;
#pragma unroll
        for (int y8 = 0; y8 < RY; ++y8) {
            const int y = Y0 + y8;
            float* b0p = out + (((size_t)co0 * CIN + ci) * HH + y) * WW + px;
            float* b1p = b0p + plane;
            b0p[0] = acc[s][y8][0] + bv;
            b1p[0] = acc[s][y8][1] + bv;
            b0p[8] = acc[s][y8][2] + bv;
            b1p[8] = acc[s][y8][3] + bv;
        }
    }
}

extern "C" void kernel_launch(void* const* d_in, const int* in_sizes, int n_in,
                              void* d_out, int out_size)
{
    const float* sig  = (const float*)d_in[0];   // [1, 8, 1024, 1024]
    const float* wgt  = (const float*)d_in[1];   // [8, 8, 31, 31]
    const float* bias = (const float*)d_in[2];   // [8]
    float* out = (float*)d_out;                  // [8, 8, 1024, 1024]

    cudaFuncSetAttribute(conv_mma_kernel,
                         cudaFuncAttributeMaxDynamicSharedMemorySize, SMEM_TOTAL);
    dim3 grid(WW / TXC, HH / RY, CIN);           // (4, 128, 8) = 4096 blocks
    conv_mma_kernel<<<grid, NT, SMEM_TOTAL>>>(sig, wgt, bias, out);
}